// round 5
// baseline (speedup 1.0000x reference)
#include <cuda_runtime.h>
#include <cstdint>

#define EPSV 1e-5f
constexpr int BB = 32, CIN = 240, C1 = 24, HH = 56, WWD = 56, HW = 3136;
constexpr int OUP = 240;
constexpr int KSPLIT = 120;

// Scratch — __device__ globals per allocation rules.
__device__ float g_pa[BB * C1 * HW];   // conv1x1 raw partial, k in [0,120)
__device__ float g_pb[BB * C1 * HW];   // conv1x1 raw partial, k in [120,240)
__device__ float g_s2[BB * C1 * HW];   // after dw3x3 + bn2 (== x1)

using u64 = unsigned long long;

__device__ __forceinline__ u64 pk2(float lo, float hi) {
    u64 r; asm("mov.b64 %0, {%1,%2};" : "=l"(r) : "f"(lo), "f"(hi)); return r;
}
__device__ __forceinline__ float2 up2(u64 v) {
    float2 f; asm("mov.b64 {%0,%1}, %2;" : "=f"(f.x), "=f"(f.y) : "l"(v)); return f;
}
__device__ __forceinline__ u64 fma2(u64 a, u64 b, u64 c) {
    u64 d; asm("fma.rn.f32x2 %0, %1, %2, %3;" : "=l"(d) : "l"(a), "l"(b), "l"(c)); return d;
}
__device__ __forceinline__ u64 add2(u64 a, u64 b) {
    u64 d; asm("add.rn.f32x2 %0, %1, %2;" : "=l"(d) : "l"(a), "l"(b)); return d;
}

// ---------------------------------------------------------------------------
// Kernel A: 1x1 conv raw partial sums, split-K (blockIdx.y = K-half).
// PIXEL-packed f32x2: thread = 12 channels x 4 pixels (2 px-pairs).
// Weight = duplicated {w,w} via LDS.64 broadcast (2 cyc) reused by 2 FFMA2
// -> crossbar at 50% of fma pipe instead of 100%.
// Block = 128 thr = 2 channel-halves x 64 px-quads (x float4s shared via L1).
// ---------------------------------------------------------------------------
__global__ __launch_bounds__(128) void kA(
    const float* __restrict__ x, const float* __restrict__ w) {
    __shared__ u64 ws[KSPLIT * C1];         // [k][c] = {w[c][k], w[c][k]}, 23 KB
    int tid = threadIdx.x;
    int half = blockIdx.y;
    int kbase = half * KSPLIT;
    for (int i = tid; i < KSPLIT * C1; i += 128) {
        int k = i / C1, c = i % C1;
        float wv = w[c * CIN + kbase + k];
        ws[i] = pk2(wv, wv);
    }
    __syncthreads();

    int chb = (tid >> 6) * 12;              // channel half: 0 or 12
    int pq = blockIdx.x * 64 + (tid & 63);  // pixel-quad id, 25088 total
    int p0 = pq * 4;
    int b = p0 / HW;
    int s = p0 - b * HW;
    const float* xp = x + (size_t)b * CIN * HW + (size_t)kbase * HW + s;

    u64 acc0[12], acc1[12];
#pragma unroll
    for (int c = 0; c < 12; c++) { acc0[c] = 0ull; acc1[c] = 0ull; }

    for (int k0 = 0; k0 < KSPLIT; k0 += 4) {
        float4 xv[4];
#pragma unroll
        for (int j = 0; j < 4; j++)
            xv[j] = *reinterpret_cast<const float4*>(xp + (size_t)(k0 + j) * HW);
#pragma unroll
        for (int j = 0; j < 4; j++) {
            u64 xa = pk2(xv[j].x, xv[j].y);
            u64 xb = pk2(xv[j].z, xv[j].w);
            const u64* wk = ws + (k0 + j) * C1 + chb;
#pragma unroll
            for (int c = 0; c < 12; c++) {
                u64 wv = wk[c];
                acc0[c] = fma2(xa, wv, acc0[c]);
                acc1[c] = fma2(xb, wv, acc1[c]);
            }
        }
    }
    float* op = (half ? g_pb : g_pa) + (size_t)b * C1 * HW + (size_t)chb * HW + s;
#pragma unroll
    for (int c = 0; c < 12; c++) {
        float2 f0 = up2(acc0[c]), f1 = up2(acc1[c]);
        *reinterpret_cast<float4*>(op + (size_t)c * HW) =
            make_float4(f0.x, f0.y, f1.x, f1.y);
    }
}

// ---------------------------------------------------------------------------
// Kernel B: merge partials + BN1, depthwise 3x3 + BN2. One q (4px) per thread.
// Flat grid 2352 x 256. Writes g_s2 (for kC, via L2) and out channels [0,24).
// ---------------------------------------------------------------------------
__global__ __launch_bounds__(256) void kB(
    const float* __restrict__ g1, const float* __restrict__ b1,
    const float* __restrict__ m1, const float* __restrict__ v1,
    const float* __restrict__ wdw,
    const float* __restrict__ g2, const float* __restrict__ b2,
    const float* __restrict__ m2, const float* __restrict__ v2,
    float* __restrict__ out) {
    int idx = blockIdx.x * 256 + threadIdx.x;   // 602112 = 32*24*784
    int q = idx % 784;
    int c = (idx / 784) % C1;
    int b = idx / (784 * C1);
    int h = q / 14;
    int w0 = (q % 14) * 4;
    float iv1 = g1[c] * rsqrtf(v1[c] + EPSV);
    float bi1 = b1[c] - m1[c] * iv1;
    size_t poff = ((size_t)b * C1 + c) * HW;
    const float* pa = g_pa + poff;
    const float* pb = g_pb + poff;

    float rb[3][6];
#pragma unroll
    for (int dy = 0; dy < 3; dy++) {
        int hh = h + dy - 1;
        bool hok = (hh >= 0) && (hh < HH);
#pragma unroll
        for (int jx = 0; jx < 6; jx++) {
            int ww = w0 + jx - 1;
            int id2 = hh * WWD + ww;
            rb[dy][jx] = (hok && ww >= 0 && ww < WWD)
                           ? fmaf(pa[id2] + pb[id2], iv1, bi1) : 0.0f;
        }
    }
    float wv[9];
#pragma unroll
    for (int t = 0; t < 9; t++) wv[t] = __ldg(wdw + c * 9 + t);
    float acc[4] = {0.f, 0.f, 0.f, 0.f};
#pragma unroll
    for (int dy = 0; dy < 3; dy++)
#pragma unroll
        for (int dx = 0; dx < 3; dx++) {
            float t = wv[dy * 3 + dx];
#pragma unroll
            for (int j = 0; j < 4; j++) acc[j] = fmaf(rb[dy][dx + j], t, acc[j]);
        }
    float iv2 = g2[c] * rsqrtf(v2[c] + EPSV);
    float bi2 = b2[c] - m2[c] * iv2;
    float4 o = make_float4(fmaf(acc[0], iv2, bi2), fmaf(acc[1], iv2, bi2),
                           fmaf(acc[2], iv2, bi2), fmaf(acc[3], iv2, bi2));
    size_t off = poff + h * WWD + w0;
    *reinterpret_cast<float4*>(g_s2 + off) = o;
    size_t ooff = ((size_t)b * OUP + c) * HW + h * WWD + w0;
    *reinterpret_cast<float4*>(out + ooff) = o;
}

// ---------------------------------------------------------------------------
// Kernel C: adder depthwise (24 -> 216) + BN3 + ReLU into out channels [24,240).
// One q (4px) per thread, grid (7, 24, 32) x 128. Reads g_s2 from L2.
// ---------------------------------------------------------------------------
__global__ __launch_bounds__(128) void kC(
    const float* __restrict__ wadd,
    const float* __restrict__ g3, const float* __restrict__ b3,
    const float* __restrict__ m3, const float* __restrict__ v3,
    float* __restrict__ out) {
    int c = blockIdx.y;
    int b = blockIdx.z;
    __shared__ u64 negtap[81];
    __shared__ float sninv[9], sbias[9];
    int tid = threadIdx.x;
    if (tid < 81) {
        float tv = wadd[c * 81 + tid];
        negtap[tid] = pk2(-tv, -tv);
    }
    if (tid < 9) {
        int ch = c * 9 + tid;
        float iv = g3[ch] * rsqrtf(v3[ch] + EPSV);
        sninv[tid] = -iv;
        sbias[tid] = b3[ch] - m3[ch] * iv;
    }
    __syncthreads();
    int q = blockIdx.x * 128 + tid;
    if (q >= 784) return;
    int h = q / 14;
    int w0 = (q % 14) * 4;
    const float* p = g_s2 + ((size_t)b * C1 + c) * HW;

    float rb[3][6];
#pragma unroll
    for (int dy = 0; dy < 3; dy++) {
        int hh = h + dy - 1;
        bool hok = (hh >= 0) && (hh < HH);
#pragma unroll
        for (int jx = 0; jx < 6; jx++) {
            int ww = w0 + jx - 1;
            rb[dy][jx] = (hok && ww >= 0 && ww < WWD) ? p[hh * WWD + ww] : 0.0f;
        }
    }
    u64 nA[9], nB[9];
#pragma unroll
    for (int dy = 0; dy < 3; dy++)
#pragma unroll
        for (int dx = 0; dx < 3; dx++) {
            nA[dy * 3 + dx] = pk2(rb[dy][dx],     rb[dy][dx + 1]);
            nB[dy * 3 + dx] = pk2(rb[dy][dx + 2], rb[dy][dx + 3]);
        }
    size_t obase = ((size_t)b * OUP + C1 + c * 9) * HW + h * WWD + w0;
#pragma unroll
    for (int r = 0; r < 9; r++) {
        u64 aA = 0ull, aB = 0ull;
#pragma unroll
        for (int t = 0; t < 9; t++) {
            u64 nt = negtap[r * 9 + t];
            u64 dA = add2(nA[t], nt) & 0x7FFFFFFF7FFFFFFFull;
            u64 dB = add2(nB[t], nt) & 0x7FFFFFFF7FFFFFFFull;
            aA = add2(aA, dA);
            aB = add2(aB, dB);
        }
        float2 fa = up2(aA), fb = up2(aB);
        float ni = sninv[r], bi = sbias[r];
        float4 o = make_float4(fmaxf(fmaf(fa.x, ni, bi), 0.f),
                               fmaxf(fmaf(fa.y, ni, bi), 0.f),
                               fmaxf(fmaf(fb.x, ni, bi), 0.f),
                               fmaxf(fmaf(fb.y, ni, bi), 0.f));
        *reinterpret_cast<float4*>(out + obase + (size_t)r * HW) = o;
    }
}

extern "C" void kernel_launch(void* const* d_in, const int* in_sizes, int n_in,
                              void* d_out, int out_size) {
    const float* x   = (const float*)d_in[0];
    const float* wp  = (const float*)d_in[1];
    const float* g1  = (const float*)d_in[2];
    const float* b1  = (const float*)d_in[3];
    const float* m1  = (const float*)d_in[4];
    const float* v1  = (const float*)d_in[5];
    const float* wdw = (const float*)d_in[6];
    const float* g2  = (const float*)d_in[7];
    const float* b2  = (const float*)d_in[8];
    const float* m2  = (const float*)d_in[9];
    const float* v2  = (const float*)d_in[10];
    const float* wa  = (const float*)d_in[11];
    const float* g3  = (const float*)d_in[12];
    const float* b3  = (const float*)d_in[13];
    const float* m3  = (const float*)d_in[14];
    const float* v3  = (const float*)d_in[15];
    float* out = (float*)d_out;

    kA<<<dim3(392, 2), 128>>>(x, wp);
    kB<<<2352, 256>>>(g1, b1, m1, v1, wdw, g2, b2, m2, v2, out);
    kC<<<dim3(7, 24, 32), 128>>>(wa, g3, b3, m3, v3, out);
}

// round 6
// speedup vs baseline: 1.6367x; 1.6367x over previous
#include <cuda_runtime.h>
#include <cstdint>

#define EPSV 1e-5f
constexpr int BB = 32, CIN = 240, C1 = 24, HH = 56, WWD = 56, HW = 3136;
constexpr int OUP = 240;
constexpr int KSPLIT = 120;

// Scratch — __device__ globals per allocation rules.
__device__ float g_pa[BB * C1 * HW];   // conv1x1 raw partial, k in [0,120)
__device__ float g_pb[BB * C1 * HW];   // conv1x1 raw partial, k in [120,240)
__device__ float g_s2[BB * C1 * HW];   // after dw3x3 + bn2 (== x1)

using u64 = unsigned long long;

__device__ __forceinline__ u64 pk2(float lo, float hi) {
    u64 r; asm("mov.b64 %0, {%1,%2};" : "=l"(r) : "f"(lo), "f"(hi)); return r;
}
__device__ __forceinline__ float2 up2(u64 v) {
    float2 f; asm("mov.b64 {%0,%1}, %2;" : "=f"(f.x), "=f"(f.y) : "l"(v)); return f;
}
__device__ __forceinline__ u64 fma2(u64 a, u64 b, u64 c) {
    u64 d; asm("fma.rn.f32x2 %0, %1, %2, %3;" : "=l"(d) : "l"(a), "l"(b), "l"(c)); return d;
}
__device__ __forceinline__ u64 add2(u64 a, u64 b) {
    u64 d; asm("add.rn.f32x2 %0, %1, %2;" : "=l"(d) : "l"(a), "l"(b)); return d;
}

// ---------------------------------------------------------------------------
// Kernel A: 1x1 conv raw partial sums.
// grid (196 px-tiles, 2 ch-halves, 2 K-halves), 128 thr.
// Thread = 4 pixels x 12 channels: 24 pixel-packed f32x2 accumulators.
// Weights: LDS.64 broadcast of dup {w,w} pairs -> 1 wavefront each
//   => 16 L1 wf per warp-k vs 12 fma-cyc (R4 was 13 wf vs 6).
// x: LDG.128 per k, 2-k double-buffered prefetch to hide DRAM latency.
// ---------------------------------------------------------------------------
__global__ __launch_bounds__(128, 6) void kA(
    const float* __restrict__ x, const float* __restrict__ w) {
    __shared__ u64 ws[KSPLIT * 12];         // [k][c] = {w,w}, 11.25 KB
    int tid = threadIdx.x;
    int chb = blockIdx.y * 12;              // channel half base
    int kbase = blockIdx.z * KSPLIT;        // K half base
    for (int i = tid; i < KSPLIT * 12; i += 128) {
        int k = i / 12, c = i % 12;
        float wv = w[(chb + c) * CIN + kbase + k];
        ws[i] = pk2(wv, wv);
    }
    __syncthreads();

    int p0 = (blockIdx.x * 128 + tid) * 4;  // 4 contiguous px (no batch cross)
    int b = p0 / HW;
    int s = p0 - b * HW;
    const float* xp = x + (size_t)b * CIN * HW + (size_t)kbase * HW + s;

    u64 acc0[12], acc1[12];
#pragma unroll
    for (int c = 0; c < 12; c++) { acc0[c] = 0ull; acc1[c] = 0ull; }

    float4 cur0 = *reinterpret_cast<const float4*>(xp);
    float4 cur1 = *reinterpret_cast<const float4*>(xp + HW);
#pragma unroll 2
    for (int k0 = 0; k0 < KSPLIT; k0 += 2) {
        int kn = (k0 + 2 == KSPLIT) ? 0 : (k0 + 2);   // clamp (redundant L1 hit)
        float4 n0 = *reinterpret_cast<const float4*>(xp + (size_t)kn * HW);
        float4 n1 = *reinterpret_cast<const float4*>(xp + (size_t)(kn + 1) * HW);
        {
            u64 xa = pk2(cur0.x, cur0.y);
            u64 xb = pk2(cur0.z, cur0.w);
            const u64* wk = ws + k0 * 12;
#pragma unroll
            for (int c = 0; c < 12; c++) {
                u64 wv = wk[c];
                acc0[c] = fma2(xa, wv, acc0[c]);
                acc1[c] = fma2(xb, wv, acc1[c]);
            }
        }
        {
            u64 xa = pk2(cur1.x, cur1.y);
            u64 xb = pk2(cur1.z, cur1.w);
            const u64* wk = ws + (k0 + 1) * 12;
#pragma unroll
            for (int c = 0; c < 12; c++) {
                u64 wv = wk[c];
                acc0[c] = fma2(xa, wv, acc0[c]);
                acc1[c] = fma2(xb, wv, acc1[c]);
            }
        }
        cur0 = n0; cur1 = n1;
    }
    float* op = (blockIdx.z ? g_pb : g_pa)
                + ((size_t)b * C1 + chb) * HW + s;
#pragma unroll
    for (int c = 0; c < 12; c++) {
        float2 f0 = up2(acc0[c]), f1 = up2(acc1[c]);
        *reinterpret_cast<float4*>(op + (size_t)c * HW) =
            make_float4(f0.x, f0.y, f1.x, f1.y);
    }
}

// ---------------------------------------------------------------------------
// Kernel B: merge partials + BN1, depthwise 3x3 + BN2. One q (4px) per thread.
// Flat grid 2352 x 256. Writes g_s2 (for kC, via L2) and out channels [0,24).
// ---------------------------------------------------------------------------
__global__ __launch_bounds__(256) void kB(
    const float* __restrict__ g1, const float* __restrict__ b1,
    const float* __restrict__ m1, const float* __restrict__ v1,
    const float* __restrict__ wdw,
    const float* __restrict__ g2, const float* __restrict__ b2,
    const float* __restrict__ m2, const float* __restrict__ v2,
    float* __restrict__ out) {
    int idx = blockIdx.x * 256 + threadIdx.x;   // 602112 = 32*24*784
    int q = idx % 784;
    int c = (idx / 784) % C1;
    int b = idx / (784 * C1);
    int h = q / 14;
    int w0 = (q % 14) * 4;
    float iv1 = g1[c] * rsqrtf(v1[c] + EPSV);
    float bi1 = b1[c] - m1[c] * iv1;
    size_t poff = ((size_t)b * C1 + c) * HW;
    const float* pa = g_pa + poff;
    const float* pb = g_pb + poff;

    float rb[3][6];
#pragma unroll
    for (int dy = 0; dy < 3; dy++) {
        int hh = h + dy - 1;
        bool hok = (hh >= 0) && (hh < HH);
#pragma unroll
        for (int jx = 0; jx < 6; jx++) {
            int ww = w0 + jx - 1;
            int id2 = hh * WWD + ww;
            rb[dy][jx] = (hok && ww >= 0 && ww < WWD)
                           ? fmaf(pa[id2] + pb[id2], iv1, bi1) : 0.0f;
        }
    }
    float wv[9];
#pragma unroll
    for (int t = 0; t < 9; t++) wv[t] = __ldg(wdw + c * 9 + t);
    float acc[4] = {0.f, 0.f, 0.f, 0.f};
#pragma unroll
    for (int dy = 0; dy < 3; dy++)
#pragma unroll
        for (int dx = 0; dx < 3; dx++) {
            float t = wv[dy * 3 + dx];
#pragma unroll
            for (int j = 0; j < 4; j++) acc[j] = fmaf(rb[dy][dx + j], t, acc[j]);
        }
    float iv2 = g2[c] * rsqrtf(v2[c] + EPSV);
    float bi2 = b2[c] - m2[c] * iv2;
    float4 o = make_float4(fmaf(acc[0], iv2, bi2), fmaf(acc[1], iv2, bi2),
                           fmaf(acc[2], iv2, bi2), fmaf(acc[3], iv2, bi2));
    size_t off = poff + h * WWD + w0;
    *reinterpret_cast<float4*>(g_s2 + off) = o;
    size_t ooff = ((size_t)b * OUP + c) * HW + h * WWD + w0;
    *reinterpret_cast<float4*>(out + ooff) = o;
}

// ---------------------------------------------------------------------------
// Kernel C: adder depthwise (24 -> 216) + BN3 + ReLU into out channels [24,240).
// One q (4px) per thread, grid (7, 24, 32) x 128. Reads g_s2 from L2.
// ---------------------------------------------------------------------------
__global__ __launch_bounds__(128) void kC(
    const float* __restrict__ wadd,
    const float* __restrict__ g3, const float* __restrict__ b3,
    const float* __restrict__ m3, const float* __restrict__ v3,
    float* __restrict__ out) {
    int c = blockIdx.y;
    int b = blockIdx.z;
    __shared__ u64 negtap[81];
    __shared__ float sninv[9], sbias[9];
    int tid = threadIdx.x;
    if (tid < 81) {
        float tv = wadd[c * 81 + tid];
        negtap[tid] = pk2(-tv, -tv);
    }
    if (tid < 9) {
        int ch = c * 9 + tid;
        float iv = g3[ch] * rsqrtf(v3[ch] + EPSV);
        sninv[tid] = -iv;
        sbias[tid] = b3[ch] - m3[ch] * iv;
    }
    __syncthreads();
    int q = blockIdx.x * 128 + tid;
    if (q >= 784) return;
    int h = q / 14;
    int w0 = (q % 14) * 4;
    const float* p = g_s2 + ((size_t)b * C1 + c) * HW;

    float rb[3][6];
#pragma unroll
    for (int dy = 0; dy < 3; dy++) {
        int hh = h + dy - 1;
        bool hok = (hh >= 0) && (hh < HH);
#pragma unroll
        for (int jx = 0; jx < 6; jx++) {
            int ww = w0 + jx - 1;
            rb[dy][jx] = (hok && ww >= 0 && ww < WWD) ? p[hh * WWD + ww] : 0.0f;
        }
    }
    u64 nA[9], nB[9];
#pragma unroll
    for (int dy = 0; dy < 3; dy++)
#pragma unroll
        for (int dx = 0; dx < 3; dx++) {
            nA[dy * 3 + dx] = pk2(rb[dy][dx],     rb[dy][dx + 1]);
            nB[dy * 3 + dx] = pk2(rb[dy][dx + 2], rb[dy][dx + 3]);
        }
    size_t obase = ((size_t)b * OUP + C1 + c * 9) * HW + h * WWD + w0;
#pragma unroll
    for (int r = 0; r < 9; r++) {
        u64 aA = 0ull, aB = 0ull;
#pragma unroll
        for (int t = 0; t < 9; t++) {
            u64 nt = negtap[r * 9 + t];
            u64 dA = add2(nA[t], nt) & 0x7FFFFFFF7FFFFFFFull;
            u64 dB = add2(nB[t], nt) & 0x7FFFFFFF7FFFFFFFull;
            aA = add2(aA, dA);
            aB = add2(aB, dB);
        }
        float2 fa = up2(aA), fb = up2(aB);
        float ni = sninv[r], bi = sbias[r];
        float4 o = make_float4(fmaxf(fmaf(fa.x, ni, bi), 0.f),
                               fmaxf(fmaf(fa.y, ni, bi), 0.f),
                               fmaxf(fmaf(fb.x, ni, bi), 0.f),
                               fmaxf(fmaf(fb.y, ni, bi), 0.f));
        *reinterpret_cast<float4*>(out + obase + (size_t)r * HW) = o;
    }
}

extern "C" void kernel_launch(void* const* d_in, const int* in_sizes, int n_in,
                              void* d_out, int out_size) {
    const float* x   = (const float*)d_in[0];
    const float* wp  = (const float*)d_in[1];
    const float* g1  = (const float*)d_in[2];
    const float* b1  = (const float*)d_in[3];
    const float* m1  = (const float*)d_in[4];
    const float* v1  = (const float*)d_in[5];
    const float* wdw = (const float*)d_in[6];
    const float* g2  = (const float*)d_in[7];
    const float* b2  = (const float*)d_in[8];
    const float* m2  = (const float*)d_in[9];
    const float* v2  = (const float*)d_in[10];
    const float* wa  = (const float*)d_in[11];
    const float* g3  = (const float*)d_in[12];
    const float* b3  = (const float*)d_in[13];
    const float* m3  = (const float*)d_in[14];
    const float* v3  = (const float*)d_in[15];
    float* out = (float*)d_out;

    kA<<<dim3(196, 2, 2), 128>>>(x, wp);
    kB<<<2352, 256>>>(g1, b1, m1, v1, wdw, g2, b2, m2, v2, out);
    kC<<<dim3(7, 24, 32), 128>>>(wa, g3, b3, m3, v3, out);
}